// round 6
// baseline (speedup 1.0000x reference)
#include <cuda_runtime.h>
#include <cuda_bf16.h>
#include <cstdint>

// ---------------------------------------------------------------------------
// SEE block, fully fused on GB300.
// One block per (batch, T-chunk): in-block bf16 mma GEMM (pointwise conv)
// into an smem bf16 tile -> depthwise conv+BN+LIF1 (smem) -> spike masks in
// smem -> sparse linear+BN+LIF2+residual -> out. No intermediate global
// tensor. Speculative T-chunking (LIF contraction 0.5/step).
// B=64, T=1000, F=140, D=256, K=7, tau=2, v_th=1, hard reset.
// ---------------------------------------------------------------------------

#define B_    64
#define T_    1000
#define F_    140
#define D_    256
#define K_    7
#define NCH   10
#define CLEN  100
#define WARM1 16        // lif1 speculative warmup
#define WARM2 16        // lif2 speculative warmup
#define MROWS 144       // y rows held in smem (3 passes x 48)
#define YSTR  132       // u32 words per y row (264 bf16, conflict-free pad)
#define ASTR  12        // A staging row stride (u32)
#define BSTR  12        // B staging row stride (u32)
#define NMASK 116       // mask rows (WARM2 + CLEN)

// u32 offsets inside dynamic smem
#define OFF_Y    0
#define OFF_B0   (OFF_Y + MROWS * YSTR)          // 19008
#define OFF_B1   (OFF_B0 + 256 * BSTR)           // +3072
#define OFF_A0   (OFF_B1 + 256 * BSTR)           // +3072
#define OFF_A1   (OFF_A0 + 48 * ASTR)            // +576
#define OFF_MSK  (OFF_A1 + 48 * ASTR)            // +576
#define OFF_ANY  (OFF_MSK + NMASK * 8)           // +928
#define SMEM_U32 (OFF_ANY + 1)
#define SMEM_BYTES (SMEM_U32 * 4)

__device__ unsigned g_wbf[9 * 256 * 8];   // pw_w bf16, frag-ready per k-step
__device__ float    g_linT[D_ * D_];      // lin_w transposed [d][e]

__device__ __forceinline__ unsigned pack_bf16(float lo, float hi) {
    __nv_bfloat162 h = __floats2bfloat162_rn(lo, hi);
    return *reinterpret_cast<unsigned*>(&h);
}

// ---------------------------------------------------------------------------
// prep: transpose lin_w; pack pw_w into bf16 k-step fragments (zero-padded)
// ---------------------------------------------------------------------------
__global__ void k_prep(const float* __restrict__ linw,
                       const float* __restrict__ w) {
    int d = blockIdx.x, e = threadIdx.x;
    g_linT[d * D_ + e] = linw[e * D_ + d];
    if (d < 9) {
        #pragma unroll
        for (int j = 0; j < 8; j++) {
            int k = d * 16 + 2 * j;
            float lo = (k     < F_) ? w[e * F_ + k]     : 0.f;
            float hi = (k + 1 < F_) ? w[e * F_ + k + 1] : 0.f;
            g_wbf[(d * 256 + e) * 8 + j] = pack_bf16(lo, hi);
        }
    }
}

// ---------------------------------------------------------------------------
// fused kernel: grid (B, NCH) x 256 threads
// ---------------------------------------------------------------------------
__global__ void __launch_bounds__(256, 2)
k_fused(const float* __restrict__ x,
        const float* __restrict__ pw_b,
        const float* __restrict__ dw,
        const float* __restrict__ g1, const float* __restrict__ b1,
        const float* __restrict__ m1, const float* __restrict__ v1,
        const float* __restrict__ g2, const float* __restrict__ b2,
        const float* __restrict__ m2, const float* __restrict__ v2p,
        float* __restrict__ out) {
    extern __shared__ unsigned shm[];
    unsigned* ySw  = shm + OFF_Y;
    unsigned* smk  = shm + OFF_MSK;
    unsigned* sany = shm + OFF_ANY;
    __nv_bfloat16* yb = reinterpret_cast<__nv_bfloat16*>(ySw);

    const int tid  = threadIdx.x;
    const int b    = blockIdx.x;
    const int ch   = blockIdx.y;
    const int warp = tid >> 5, lane = tid & 31;
    const int g    = lane >> 2, tig = lane & 3;
    const int wn   = warp;                    // 8 warps, 32 n-cols each

    const int tstart = ch * CLEN;
    const int tend   = tstart + CLEN;
    const int ts2    = (ch == 0) ? 0 : tstart - WARM2;
    const int ts1    = (ch == 0) ? 0 : ts2 - WARM1;
    const int tbase  = ts1 - 3;               // global t of yS row 0

    if (tid == 0) *sany = 0u;
    // zero the y tile (covers padded / out-of-range rows)
    for (int i = tid; i < MROWS * YSTR; i += 256) ySw[i] = 0u;

    // bias per output column (folded into stored y at epilogue)
    float bias_lo[4], bias_hi[4];
    #pragma unroll
    for (int ni = 0; ni < 4; ni++) {
        int col = wn * 32 + ni * 8 + 2 * tig;
        bias_lo[ni] = pw_b[col];
        bias_hi[ni] = pw_b[col + 1];
    }
    __syncthreads();

    // ---------------- GEMM: y[t, n] = x[b,t,:] . pw_w[n,:] + bias ---------
    const int ar = tid >> 2, aq = tid & 3;    // A staging coords (tid<192)
    float4 pa;
    uint4  pb0, pb1;

    for (int pass = 0; pass < 3; ++pass) {
        const int rbase = pass * 48;

        float c[3][4][4];
        #pragma unroll
        for (int mi = 0; mi < 3; mi++)
            #pragma unroll
            for (int ni = 0; ni < 4; ni++)
                #pragma unroll
                for (int r = 0; r < 4; r++) c[mi][ni][r] = 0.f;

        auto ldA = [&](int s) {
            if (tid < 192) {
                int k = s * 16 + aq * 4;
                int t = tbase + rbase + ar;
                if (k < F_ && t >= 0 && t < T_)
                    pa = *(const float4*)&x[((size_t)b * T_ + t) * F_ + k];
                else
                    pa = make_float4(0.f, 0.f, 0.f, 0.f);
            }
        };
        auto stA = [&](unsigned* Abuf) {
            if (tid < 192) {
                Abuf[ar * ASTR + aq * 2]     = pack_bf16(pa.x, pa.y);
                Abuf[ar * ASTR + aq * 2 + 1] = pack_bf16(pa.z, pa.w);
            }
        };
        auto ldB = [&](int s) {
            const uint4* src = (const uint4*)&g_wbf[((size_t)s * 256 + tid) * 8];
            pb0 = src[0]; pb1 = src[1];
        };
        auto stB = [&](unsigned* Bbuf) {
            uint4* dst = (uint4*)&Bbuf[tid * BSTR];
            dst[0] = pb0; dst[1] = pb1;
        };

        ldA(0); ldB(0);
        stA(shm + OFF_A0); stB(shm + OFF_B0);
        __syncthreads();

        int p = 0;
        for (int s = 0; s < 9; ++s) {
            if (s < 8) { ldA(s + 1); ldB(s + 1); }

            unsigned* Ab = shm + (p ? OFF_A1 : OFF_A0);
            unsigned* Bb = shm + (p ? OFF_B1 : OFF_B0);

            unsigned a[3][4], bf[4][2];
            #pragma unroll
            for (int mi = 0; mi < 3; mi++) {
                int r = mi * 16;
                a[mi][0] = Ab[(r + g) * ASTR + tig];
                a[mi][1] = Ab[(r + g + 8) * ASTR + tig];
                a[mi][2] = Ab[(r + g) * ASTR + tig + 4];
                a[mi][3] = Ab[(r + g + 8) * ASTR + tig + 4];
            }
            #pragma unroll
            for (int ni = 0; ni < 4; ni++) {
                int cb = wn * 32 + ni * 8;
                bf[ni][0] = Bb[(cb + g) * BSTR + tig];
                bf[ni][1] = Bb[(cb + g) * BSTR + tig + 4];
            }
            #pragma unroll
            for (int mi = 0; mi < 3; mi++)
                #pragma unroll
                for (int ni = 0; ni < 4; ni++) {
                    asm volatile(
                        "mma.sync.aligned.m16n8k16.row.col.f32.bf16.bf16.f32 "
                        "{%0,%1,%2,%3}, {%4,%5,%6,%7}, {%8,%9}, {%0,%1,%2,%3};\n"
                        : "+f"(c[mi][ni][0]), "+f"(c[mi][ni][1]),
                          "+f"(c[mi][ni][2]), "+f"(c[mi][ni][3])
                        : "r"(a[mi][0]), "r"(a[mi][1]),
                          "r"(a[mi][2]), "r"(a[mi][3]),
                          "r"(bf[ni][0]), "r"(bf[ni][1]));
                }

            if (s < 8) {
                stA(shm + (p ? OFF_A0 : OFF_A1));
                stB(shm + (p ? OFF_B0 : OFF_B1));
            }
            __syncthreads();
            p ^= 1;
        }

        // epilogue: +bias, pack bf16 into yS (rows with invalid t stay zero)
        #pragma unroll
        for (int mi = 0; mi < 3; mi++) {
            int r0 = rbase + mi * 16 + g;
            int t0 = tbase + r0;
            #pragma unroll
            for (int ni = 0; ni < 4; ni++) {
                int word = wn * 16 + ni * 4 + tig;
                if (t0 >= 0 && t0 < T_)
                    ySw[r0 * YSTR + word] =
                        pack_bf16(c[mi][ni][0] + bias_lo[ni],
                                  c[mi][ni][1] + bias_hi[ni]);
                if (t0 + 8 >= 0 && t0 + 8 < T_)
                    ySw[(r0 + 8) * YSTR + word] =
                        pack_bf16(c[mi][ni][2] + bias_lo[ni],
                                  c[mi][ni][3] + bias_hi[ni]);
            }
        }
    }
    __syncthreads();

    // ---------------- phase 1: depthwise conv + BN1 + LIF1 ----------------
    {
        const int d = tid;
        const float scale = g1[d] * rsqrtf(v1[d] + 1e-5f);
        const float shift = b1[d] - m1[d] * scale;
        float ac[K_];
        #pragma unroll
        for (int k = 0; k < K_; k++) ac[k] = 0.5f * scale * dw[d * K_ + k];
        const float base = 0.5f * shift;

        // window rows 0..6 = t in [ts1-3, ts1+3]
        float w0 = __bfloat162float(yb[0 * (YSTR * 2) + d]);
        float w1 = __bfloat162float(yb[1 * (YSTR * 2) + d]);
        float w2 = __bfloat162float(yb[2 * (YSTR * 2) + d]);
        float w3 = __bfloat162float(yb[3 * (YSTR * 2) + d]);
        float w4 = __bfloat162float(yb[4 * (YSTR * 2) + d]);
        float w5 = __bfloat162float(yb[5 * (YSTR * 2) + d]);
        float w6 = __bfloat162float(yb[6 * (YSTR * 2) + d]);

        float v = 0.f;
        // speculative warmup [ts1, ts2): no mask writes (empty for ch 0)
        for (int t = ts1; t < ts2; ++t) {
            float acc = base;
            acc = fmaf(w0, ac[0], acc); acc = fmaf(w1, ac[1], acc);
            acc = fmaf(w2, ac[2], acc); acc = fmaf(w3, ac[3], acc);
            acc = fmaf(w4, ac[4], acc); acc = fmaf(w5, ac[5], acc);
            acc = fmaf(w6, ac[6], acc);
            v = fmaf(v, 0.5f, acc);
            if (v >= 1.0f) v = 0.f;
            float nf = __bfloat162float(yb[(t + 4 - tbase) * (YSTR * 2) + d]);
            w0 = w1; w1 = w2; w2 = w3; w3 = w4; w4 = w5; w5 = w6; w6 = nf;
        }

        unsigned locOr = 0u;
        #pragma unroll 4
        for (int t = ts2; t < tend; ++t) {
            float acc = base;
            acc = fmaf(w0, ac[0], acc); acc = fmaf(w1, ac[1], acc);
            acc = fmaf(w2, ac[2], acc); acc = fmaf(w3, ac[3], acc);
            acc = fmaf(w4, ac[4], acc); acc = fmaf(w5, ac[5], acc);
            acc = fmaf(w6, ac[6], acc);
            v = fmaf(v, 0.5f, acc);
            bool s = (v >= 1.0f);
            unsigned bal = __ballot_sync(0xffffffffu, s);
            if (s) v = 0.f;
            if (lane == 0) { smk[(t - ts2) * 8 + warp] = bal; locOr |= bal; }
            float nf = __bfloat162float(yb[(t + 4 - tbase) * (YSTR * 2) + d]);
            w0 = w1; w1 = w2; w2 = w3; w3 = w4; w4 = w5; w5 = w6; w6 = nf;
        }
        if (lane == 0 && locOr) atomicOr(sany, locOr);
    }
    __syncthreads();

    // ---------------- phase 2: sparse linear + BN2 + LIF2 + residual ------
    const int e = tid;
    const float scale2 = g2[e] * rsqrtf(v2p[e] + 1e-5f);
    const float shift2 = b2[e] - m2[e] * scale2;

    float* op = out + (size_t)tstart * (B_ * D_) + (size_t)b * D_ + e;

    if (*sany == 0u) {
        if (shift2 < 1.0f) {
            #pragma unroll 10
            for (int j = 0; j < CLEN; ++j)
                op[(size_t)j * (B_ * D_)] = 0.f;
        } else {
            float v = 0.f;
            const float hs = 0.5f * shift2;
            for (int j = 0; j < tstart - ts2; ++j) {
                v = fmaf(v, 0.5f, hs);
                if (v >= 1.0f) v = 0.f;
            }
            #pragma unroll 10
            for (int j = 0; j < CLEN; ++j) {
                v = fmaf(v, 0.5f, hs);
                float sp = 0.f;
                if (v >= 1.0f) { sp = 1.f; v = 0.f; }
                op[(size_t)j * (B_ * D_)] = sp;
            }
        }
        return;
    }

    // slow path
    const int      myw   = e >> 5;
    const unsigned mybit = 1u << (e & 31);
    float v = 0.f;

    for (int t = ts2; t < tend; ++t) {
        const int o = (t - ts2) * 8;
        uint4 p0 = *(const uint4*)&smk[o];
        uint4 p1 = *(const uint4*)&smk[o + 4];
        unsigned any = p0.x | p0.y | p0.z | p0.w | p1.x | p1.y | p1.z | p1.w;

        float acc = 0.f, res = 0.f;
        if (any) {
            unsigned wds[8] = {p0.x, p0.y, p0.z, p0.w, p1.x, p1.y, p1.z, p1.w};
            #pragma unroll
            for (int i = 0; i < 8; i++) {
                unsigned wd = wds[i];
                if (i == myw && (wd & mybit)) res = 1.f;
                while (wd) {
                    int bit = __ffs(wd) - 1;
                    wd &= wd - 1;
                    acc += g_linT[(size_t)(i * 32 + bit) * D_ + e];
                }
            }
        }

        float u = fmaf(acc, scale2, shift2);
        v = 0.5f * (v + u);
        float sp = 0.f;
        if (v >= 1.0f) { sp = 1.f; v = 0.f; }

        if (t >= tstart)
            out[((size_t)t * B_ + b) * D_ + e] = sp + res;
    }
}

// ---------------------------------------------------------------------------
// inputs: 0:x 1:pw_w 2:pw_b 3:dw_w 4:bn1_g 5:bn1_b 6:bn1_m 7:bn1_v
//         8:lin_w 9:bn2_g 10:bn2_b 11:bn2_m 12:bn2_v
// ---------------------------------------------------------------------------
extern "C" void kernel_launch(void* const* d_in, const int* in_sizes, int n_in,
                              void* d_out, int out_size) {
    const float* x    = (const float*)d_in[0];
    const float* pw_w = (const float*)d_in[1];
    const float* pw_b = (const float*)d_in[2];
    const float* dw_w = (const float*)d_in[3];
    const float* g1   = (const float*)d_in[4];
    const float* b1   = (const float*)d_in[5];
    const float* m1   = (const float*)d_in[6];
    const float* v1   = (const float*)d_in[7];
    const float* linw = (const float*)d_in[8];
    const float* g2   = (const float*)d_in[9];
    const float* b2   = (const float*)d_in[10];
    const float* m2   = (const float*)d_in[11];
    const float* v2   = (const float*)d_in[12];
    float* out = (float*)d_out;

    cudaFuncSetAttribute(k_fused, cudaFuncAttributeMaxDynamicSharedMemorySize,
                         SMEM_BYTES);

    k_prep<<<D_, D_>>>(linw, pw_w);

    dim3 gl(B_, NCH);
    k_fused<<<gl, 256, SMEM_BYTES>>>(x, pw_b, dw_w, g1, b1, m1, v1,
                                     g2, b2, m2, v2, out);
}

// round 7
// speedup vs baseline: 1.0906x; 1.0906x over previous
#include <cuda_runtime.h>
#include <cuda_bf16.h>
#include <cstdint>

// ---------------------------------------------------------------------------
// SEE block on GB300 — split architecture (GEMM / fused-LIF).
// GEMM1: bf16 mma.sync, BM=64 BN=128, reg-prefetch double buffer, y -> bf16.
// k_lif: depthwise conv+BN+LIF1 (MLP=4 prefetch) -> masks in smem ->
//        sparse linear+BN+LIF2+residual with chunk-level zero fast path.
// B=64, T=1000, F=140, D=256, K=7, tau=2, v_th=1, hard reset.
// ---------------------------------------------------------------------------

#define B_    64
#define T_    1000
#define F_    140
#define D_    256
#define K_    7
#define NCH   10
#define CLEN  100
#define WARM1 16
#define WARM2 16
#define SMT   (CLEN + WARM2)

__device__ __nv_bfloat16 g_ybf[(size_t)B_ * T_ * D_];  // GEMM out, bf16 (32.8MB)
__device__ float         g_linT[D_ * D_];              // lin_w^T [d][e]

#define ASTR 12

__device__ __forceinline__ unsigned pack_bf16(float lo, float hi) {
    __nv_bfloat162 h = __floats2bfloat162_rn(lo, hi);
    return *reinterpret_cast<unsigned*>(&h);
}

// ---------------------------------------------------------------------------
// GEMM1: y[m,n] = x[m,:].pw_w[n,:],  M=64000 N=256 K=140, BM=64 BN=128.
// 8 warps: wm in {0,1} (32 rows), wn in {0..3} (32 cols). 9 k-steps.
// ---------------------------------------------------------------------------
__global__ __launch_bounds__(256) void k_gemm1(const float* __restrict__ x,
                                               const float* __restrict__ w,
                                               const float* __restrict__ linw) {
    __shared__ unsigned As[2][64 * ASTR];
    __shared__ unsigned Bs[2][128 * ASTR];

    const int tid = threadIdx.x;
    const int m0  = blockIdx.x * 64;
    const int n0  = blockIdx.y * 128;

    // folded transpose of lin_w (first 256 blocks of the y=0 slice)
    if (blockIdx.y == 0 && blockIdx.x < D_) {
        int d = blockIdx.x;
        g_linT[d * D_ + tid] = linw[tid * D_ + d];
    }

    const int warp = tid >> 5, lane = tid & 31;
    const int wm   = warp >> 2;
    const int wn   = warp & 3;
    const int g    = lane >> 2, tig = lane & 3;

    const int ar = tid >> 2, aq = tid & 3;           // A: 1 float4/thread
    const int br0 = tid >> 2, br1 = (tid + 256) >> 2; // B: 2 float4/thread

    float4 pa, pb0, pb1;

    auto ld_tiles = [&](int s) {
        const int k0 = s * 16;
        int ka = k0 + aq * 4;
        pa = (ka < F_) ? *(const float4*)&x[(size_t)(m0 + ar) * F_ + ka]
                       : make_float4(0.f, 0.f, 0.f, 0.f);
        pb0 = (ka < F_) ? *(const float4*)&w[(size_t)(n0 + br0) * F_ + ka]
                        : make_float4(0.f, 0.f, 0.f, 0.f);
        pb1 = (ka < F_) ? *(const float4*)&w[(size_t)(n0 + br1) * F_ + ka]
                        : make_float4(0.f, 0.f, 0.f, 0.f);
    };
    auto st_tiles = [&](int buf) {
        As[buf][ar * ASTR + aq * 2]      = pack_bf16(pa.x, pa.y);
        As[buf][ar * ASTR + aq * 2 + 1]  = pack_bf16(pa.z, pa.w);
        Bs[buf][br0 * ASTR + aq * 2]     = pack_bf16(pb0.x, pb0.y);
        Bs[buf][br0 * ASTR + aq * 2 + 1] = pack_bf16(pb0.z, pb0.w);
        Bs[buf][br1 * ASTR + aq * 2]     = pack_bf16(pb1.x, pb1.y);
        Bs[buf][br1 * ASTR + aq * 2 + 1] = pack_bf16(pb1.z, pb1.w);
    };

    float c[2][4][4];
    #pragma unroll
    for (int i = 0; i < 2; i++)
        #pragma unroll
        for (int j = 0; j < 4; j++)
            #pragma unroll
            for (int r = 0; r < 4; r++) c[i][j][r] = 0.f;

    ld_tiles(0);
    st_tiles(0);
    __syncthreads();

    int p = 0;
    for (int s = 0; s < 9; ++s) {
        if (s < 8) ld_tiles(s + 1);

        unsigned a[2][4], bf[4][2];
        #pragma unroll
        for (int mi = 0; mi < 2; mi++) {
            int r = wm * 32 + mi * 16;
            a[mi][0] = As[p][(r + g) * ASTR + tig];
            a[mi][1] = As[p][(r + g + 8) * ASTR + tig];
            a[mi][2] = As[p][(r + g) * ASTR + tig + 4];
            a[mi][3] = As[p][(r + g + 8) * ASTR + tig + 4];
        }
        #pragma unroll
        for (int ni = 0; ni < 4; ni++) {
            int cb = wn * 32 + ni * 8;
            bf[ni][0] = Bs[p][(cb + g) * ASTR + tig];
            bf[ni][1] = Bs[p][(cb + g) * ASTR + tig + 4];
        }
        #pragma unroll
        for (int mi = 0; mi < 2; mi++)
            #pragma unroll
            for (int ni = 0; ni < 4; ni++) {
                asm volatile(
                    "mma.sync.aligned.m16n8k16.row.col.f32.bf16.bf16.f32 "
                    "{%0,%1,%2,%3}, {%4,%5,%6,%7}, {%8,%9}, {%0,%1,%2,%3};\n"
                    : "+f"(c[mi][ni][0]), "+f"(c[mi][ni][1]),
                      "+f"(c[mi][ni][2]), "+f"(c[mi][ni][3])
                    : "r"(a[mi][0]), "r"(a[mi][1]), "r"(a[mi][2]), "r"(a[mi][3]),
                      "r"(bf[ni][0]), "r"(bf[ni][1]));
            }

        if (s < 8) st_tiles(1 - p);
        __syncthreads();
        p ^= 1;
    }

    // epilogue: pack bf16 pairs, store as u32
    unsigned* yw = reinterpret_cast<unsigned*>(g_ybf);
    #pragma unroll
    for (int mi = 0; mi < 2; mi++) {
        int r0 = m0 + wm * 32 + mi * 16 + g;
        #pragma unroll
        for (int ni = 0; ni < 4; ni++) {
            int col = n0 + wn * 32 + ni * 8 + 2 * tig;
            yw[((size_t)r0 * D_ + col) >> 1]       = pack_bf16(c[mi][ni][0], c[mi][ni][1]);
            yw[((size_t)(r0 + 8) * D_ + col) >> 1] = pack_bf16(c[mi][ni][2], c[mi][ni][3]);
        }
    }
}

// ---------------------------------------------------------------------------
// fused LIF kernel: grid (B, NCH) x 256 threads
// ---------------------------------------------------------------------------
template <bool GUARD>
__device__ __forceinline__ void lif1_main(const __nv_bfloat16* __restrict__ yp,
                                          const float* ac, float base,
                                          float& v, float& w0, float& w1,
                                          float& w2, float& w3, float& w4,
                                          float& w5, float& w6,
                                          int ts2, int tend, unsigned* smk,
                                          unsigned& locOr, int warp, int lane) {
    for (int t0 = ts2; t0 < tend; t0 += 4) {
        float nf[4];
        #pragma unroll
        for (int j = 0; j < 4; j++) {
            int t = t0 + 4 + j;
            if (GUARD)
                nf[j] = (t < T_) ? __bfloat162float(yp[(size_t)t * D_]) : 0.f;
            else
                nf[j] = __bfloat162float(yp[(size_t)t * D_]);
        }
        #pragma unroll
        for (int j = 0; j < 4; j++) {
            float acc = base;
            acc = fmaf(w0, ac[0], acc); acc = fmaf(w1, ac[1], acc);
            acc = fmaf(w2, ac[2], acc); acc = fmaf(w3, ac[3], acc);
            acc = fmaf(w4, ac[4], acc); acc = fmaf(w5, ac[5], acc);
            acc = fmaf(w6, ac[6], acc);
            v = fmaf(v, 0.5f, acc);
            bool s = (v >= 1.0f);
            unsigned bal = __ballot_sync(0xffffffffu, s);
            if (s) v = 0.f;
            if (lane == 0) { smk[(t0 + j - ts2) * 8 + warp] = bal; locOr |= bal; }
            w0 = w1; w1 = w2; w2 = w3; w3 = w4; w4 = w5; w5 = w6; w6 = nf[j];
        }
    }
}

__global__ __launch_bounds__(256) void k_lif(const float* __restrict__ pw_b,
                                             const float* __restrict__ dw,
                                             const float* __restrict__ g1,
                                             const float* __restrict__ b1,
                                             const float* __restrict__ m1,
                                             const float* __restrict__ v1,
                                             const float* __restrict__ g2,
                                             const float* __restrict__ b2,
                                             const float* __restrict__ m2,
                                             const float* __restrict__ v2p,
                                             float* __restrict__ out) {
    __shared__ unsigned smk[SMT * 8];
    __shared__ unsigned s_any;

    const int b    = blockIdx.x;
    const int ch   = blockIdx.y;
    const int d    = threadIdx.x;
    const int lane = d & 31;
    const int warp = d >> 5;

    const int tstart = ch * CLEN;
    const int tend   = tstart + CLEN;
    const int ts2    = (ch == 0) ? 0 : tstart - WARM2;
    const int ts1    = (ch == 0) ? 0 : ts2 - WARM1;

    if (d == 0) s_any = 0u;

    // ---- phase 1: depthwise conv + BN1 + LIF1 ----
    {
        const float bias  = pw_b[d];
        const float scale = g1[d] * rsqrtf(v1[d] + 1e-5f);
        const float shift = b1[d] - m1[d] * scale;

        float ac[K_];
        float suma = 0.f;
        #pragma unroll
        for (int k = 0; k < K_; k++) {
            float a = dw[d * K_ + k];
            suma += a;
            ac[k] = 0.5f * scale * a;
        }
        const float base = 0.5f * (scale * bias * suma + shift);

        const __nv_bfloat16* yp = g_ybf + (size_t)b * T_ * D_ + d;

        float w0, w1, w2, w3, w4, w5, w6;
        {
            float wv[7];
            #pragma unroll
            for (int j = 0; j < 7; j++) {
                int t = ts1 - 3 + j;
                wv[j] = (t >= 0) ? __bfloat162float(yp[(size_t)t * D_]) : 0.f;
            }
            w0 = wv[0]; w1 = wv[1]; w2 = wv[2]; w3 = wv[3];
            w4 = wv[4]; w5 = wv[5]; w6 = wv[6];
        }

        float v = 0.f;
        // speculative warmup [ts1, ts2): no writes; t+4 always < T here
        for (int t0 = ts1; t0 < ts2; t0 += 4) {
            float nf[4];
            #pragma unroll
            for (int j = 0; j < 4; j++)
                nf[j] = __bfloat162float(yp[(size_t)(t0 + 4 + j) * D_]);
            #pragma unroll
            for (int j = 0; j < 4; j++) {
                float acc = base;
                acc = fmaf(w0, ac[0], acc); acc = fmaf(w1, ac[1], acc);
                acc = fmaf(w2, ac[2], acc); acc = fmaf(w3, ac[3], acc);
                acc = fmaf(w4, ac[4], acc); acc = fmaf(w5, ac[5], acc);
                acc = fmaf(w6, ac[6], acc);
                v = fmaf(v, 0.5f, acc);
                if (v >= 1.0f) v = 0.f;
                w0 = w1; w1 = w2; w2 = w3; w3 = w4; w4 = w5; w5 = w6; w6 = nf[j];
            }
        }

        unsigned locOr = 0u;
        if (ch == NCH - 1)
            lif1_main<true >(yp, ac, base, v, w0, w1, w2, w3, w4, w5, w6,
                             ts2, tend, smk, locOr, warp, lane);
        else
            lif1_main<false>(yp, ac, base, v, w0, w1, w2, w3, w4, w5, w6,
                             ts2, tend, smk, locOr, warp, lane);

        if (lane == 0 && locOr) atomicOr(&s_any, locOr);
    }
    __syncthreads();

    // ---- phase 2: sparse linear + BN2 + LIF2 + residual ----
    const int e = d;
    const float scale2 = g2[e] * rsqrtf(v2p[e] + 1e-5f);
    const float shift2 = b2[e] - m2[e] * scale2;

    float* op = out + (size_t)tstart * (B_ * D_) + (size_t)b * D_ + e;

    if (s_any == 0u) {
        if (shift2 < 1.0f) {
            #pragma unroll 10
            for (int j = 0; j < CLEN; ++j)
                op[(size_t)j * (B_ * D_)] = 0.f;
        } else {
            float v = 0.f;
            const float hs = 0.5f * shift2;
            for (int j = 0; j < tstart - ts2; ++j) {
                v = fmaf(v, 0.5f, hs);
                if (v >= 1.0f) v = 0.f;
            }
            #pragma unroll 10
            for (int j = 0; j < CLEN; ++j) {
                v = fmaf(v, 0.5f, hs);
                float sp = 0.f;
                if (v >= 1.0f) { sp = 1.f; v = 0.f; }
                op[(size_t)j * (B_ * D_)] = sp;
            }
        }
        return;
    }

    // slow path: spikes present in window
    const int      myw   = e >> 5;
    const unsigned mybit = 1u << (e & 31);
    float v = 0.f;

    for (int t = ts2; t < tend; ++t) {
        const int o = (t - ts2) * 8;
        uint4 p0 = *(const uint4*)&smk[o];
        uint4 p1 = *(const uint4*)&smk[o + 4];
        unsigned any = p0.x | p0.y | p0.z | p0.w | p1.x | p1.y | p1.z | p1.w;

        float acc = 0.f, res = 0.f;
        if (any) {
            unsigned wds[8] = {p0.x, p0.y, p0.z, p0.w, p1.x, p1.y, p1.z, p1.w};
            #pragma unroll
            for (int i = 0; i < 8; i++) {
                unsigned wd = wds[i];
                if (i == myw && (wd & mybit)) res = 1.f;
                while (wd) {
                    int bit = __ffs(wd) - 1;
                    wd &= wd - 1;
                    acc += g_linT[(size_t)(i * 32 + bit) * D_ + e];
                }
            }
        }

        float u = fmaf(acc, scale2, shift2);
        v = 0.5f * (v + u);
        float sp = 0.f;
        if (v >= 1.0f) { sp = 1.f; v = 0.f; }

        if (t >= tstart)
            out[((size_t)t * B_ + b) * D_ + e] = sp + res;
    }
}

// ---------------------------------------------------------------------------
// inputs: 0:x 1:pw_w 2:pw_b 3:dw_w 4:bn1_g 5:bn1_b 6:bn1_m 7:bn1_v
//         8:lin_w 9:bn2_g 10:bn2_b 11:bn2_m 12:bn2_v
// ---------------------------------------------------------------------------
extern "C" void kernel_launch(void* const* d_in, const int* in_sizes, int n_in,
                              void* d_out, int out_size) {
    const float* x    = (const float*)d_in[0];
    const float* pw_w = (const float*)d_in[1];
    const float* pw_b = (const float*)d_in[2];
    const float* dw_w = (const float*)d_in[3];
    const float* g1   = (const float*)d_in[4];
    const float* b1   = (const float*)d_in[5];
    const float* m1   = (const float*)d_in[6];
    const float* v1   = (const float*)d_in[7];
    const float* linw = (const float*)d_in[8];
    const float* g2   = (const float*)d_in[9];
    const float* b2   = (const float*)d_in[10];
    const float* m2   = (const float*)d_in[11];
    const float* v2   = (const float*)d_in[12];
    float* out = (float*)d_out;

    dim3 gg((B_ * T_) / 64, D_ / 128);         // (1000, 2)
    k_gemm1<<<gg, 256>>>(x, pw_w, linw);

    dim3 gl(B_, NCH);
    k_lif<<<gl, 256>>>(pw_b, dw_w, g1, b1, m1, v1, g2, b2, m2, v2, out);
}

// round 8
// speedup vs baseline: 1.1198x; 1.0268x over previous
#include <cuda_runtime.h>
#include <cuda_bf16.h>
#include <cstdint>

// ---------------------------------------------------------------------------
// SEE block on GB300 — split architecture, sync-light GEMM.
// GEMM1: full-K resident smem tiles (B once/block, A per m-tile), 9 mma steps
//        with NO intra-k syncs; 4 syncs per block total. y stored bf16.
// k_lif: depthwise conv+BN+LIF1 (MLP=4) -> masks in smem -> sparse linear
//        +BN+LIF2+residual, chunk-level zero fast path. NCH=20.
// B=64, T=1000, F=140, D=256, K=7, tau=2, v_th=1, hard reset.
// ---------------------------------------------------------------------------

#define B_    64
#define T_    1000
#define F_    140
#define D_    256
#define K_    7
#define NCH   20
#define CLEN  50
#define WARM1 16
#define WARM2 16
#define SMT   72          // mask rows in smem (66 used + unroll overshoot pad)

#define MT    2           // m-tiles per GEMM block
#define KSTR  76          // u32 per smem row: 9 steps * 8 words + 4 pad
#define OFF_B 0
#define OFF_A (128 * KSTR)
#define GSM_U32 (OFF_A + 64 * KSTR)
#define GSM_BYTES (GSM_U32 * 4)

__device__ __nv_bfloat16 g_ybf[(size_t)B_ * T_ * D_];  // GEMM out (B,T,D) bf16
__device__ float         g_linT[D_ * D_];              // lin_w^T [d][e]

__device__ __forceinline__ unsigned pack_bf16(float lo, float hi) {
    __nv_bfloat162 h = __floats2bfloat162_rn(lo, hi);
    return *reinterpret_cast<unsigned*>(&h);
}

// ---------------------------------------------------------------------------
// GEMM1: y[m,n] = x[m,:].pw_w[n,:], M=64000 N=256 K=140. BM=64 BN=128 MT=2.
// grid (500, 2) x 256 thr. 8 warps: wm {0,1} x wn {0..3}.
// ---------------------------------------------------------------------------
__global__ __launch_bounds__(256) void k_gemm1(const float* __restrict__ x,
                                               const float* __restrict__ w,
                                               const float* __restrict__ linw) {
    extern __shared__ unsigned sh[];
    unsigned* Bs = sh + OFF_B;
    unsigned* As = sh + OFF_A;

    const int tid   = threadIdx.x;
    const int mbase = blockIdx.x * (MT * 64);
    const int n0    = blockIdx.y * 128;

    // folded transpose of lin_w
    if (blockIdx.y == 0 && blockIdx.x < D_) {
        int d = blockIdx.x;
        g_linT[d * D_ + tid] = linw[tid * D_ + d];
    }

    const int warp = tid >> 5, lane = tid & 31;
    const int wm = warp >> 2, wn = warp & 3;
    const int g  = lane >> 2, tig = lane & 3;

    // ---- stage full-K B tile (128 x 140 fp32 -> bf16 smem), once ----
    for (int i = tid; i < 128 * 36; i += 256) {
        int row = i / 36, q = i - row * 36;
        int k = q * 4;
        float4 f = make_float4(0.f, 0.f, 0.f, 0.f);
        if (k + 3 < F_) f = *(const float4*)&w[(size_t)(n0 + row) * F_ + k];
        int s = k >> 4, j = (k & 15) >> 2;
        Bs[row * KSTR + s * 8 + j * 2]     = pack_bf16(f.x, f.y);
        Bs[row * KSTR + s * 8 + j * 2 + 1] = pack_bf16(f.z, f.w);
    }

    // ---- A tile staging: 9 float4 per thread, reg-prefetched ----
    float4 pa[9];
    auto ldA = [&](int mt) {
        int m0 = mbase + mt * 64;
        #pragma unroll
        for (int it = 0; it < 9; it++) {
            int i = tid + it * 256;
            int row = i / 36, q = i - row * 36;
            int k = q * 4;
            pa[it] = make_float4(0.f, 0.f, 0.f, 0.f);
            if (k + 3 < F_)
                pa[it] = *(const float4*)&x[(size_t)(m0 + row) * F_ + k];
        }
    };
    auto stA = [&]() {
        #pragma unroll
        for (int it = 0; it < 9; it++) {
            int i = tid + it * 256;
            int row = i / 36, q = i - row * 36;
            int k = q * 4;
            int s = k >> 4, j = (k & 15) >> 2;
            As[row * KSTR + s * 8 + j * 2]     = pack_bf16(pa[it].x, pa[it].y);
            As[row * KSTR + s * 8 + j * 2 + 1] = pack_bf16(pa[it].z, pa[it].w);
        }
    };

    ldA(0);
    __syncthreads();        // B staged
    stA();
    __syncthreads();        // A tile 0 staged

    unsigned* yw = reinterpret_cast<unsigned*>(g_ybf);

    for (int mt = 0; mt < MT; mt++) {
        if (mt + 1 < MT) ldA(mt + 1);   // prefetch next A during mma stream

        float c[2][4][4];
        #pragma unroll
        for (int i = 0; i < 2; i++)
            #pragma unroll
            for (int j = 0; j < 4; j++)
                #pragma unroll
                for (int r = 0; r < 4; r++) c[i][j][r] = 0.f;

        #pragma unroll
        for (int s = 0; s < 9; s++) {
            unsigned a[2][4], bf[4][2];
            #pragma unroll
            for (int mi = 0; mi < 2; mi++) {
                int r = wm * 32 + mi * 16;
                a[mi][0] = As[(r + g) * KSTR + s * 8 + tig];
                a[mi][1] = As[(r + g + 8) * KSTR + s * 8 + tig];
                a[mi][2] = As[(r + g) * KSTR + s * 8 + tig + 4];
                a[mi][3] = As[(r + g + 8) * KSTR + s * 8 + tig + 4];
            }
            #pragma unroll
            for (int ni = 0; ni < 4; ni++) {
                int cb = wn * 32 + ni * 8;
                bf[ni][0] = Bs[(cb + g) * KSTR + s * 8 + tig];
                bf[ni][1] = Bs[(cb + g) * KSTR + s * 8 + tig + 4];
            }
            #pragma unroll
            for (int mi = 0; mi < 2; mi++)
                #pragma unroll
                for (int ni = 0; ni < 4; ni++) {
                    asm volatile(
                        "mma.sync.aligned.m16n8k16.row.col.f32.bf16.bf16.f32 "
                        "{%0,%1,%2,%3}, {%4,%5,%6,%7}, {%8,%9}, {%0,%1,%2,%3};\n"
                        : "+f"(c[mi][ni][0]), "+f"(c[mi][ni][1]),
                          "+f"(c[mi][ni][2]), "+f"(c[mi][ni][3])
                        : "r"(a[mi][0]), "r"(a[mi][1]),
                          "r"(a[mi][2]), "r"(a[mi][3]),
                          "r"(bf[ni][0]), "r"(bf[ni][1]));
                }
        }

        // epilogue: pack bf16 pairs, store as u32
        int m0 = mbase + mt * 64;
        #pragma unroll
        for (int mi = 0; mi < 2; mi++) {
            int r0 = m0 + wm * 32 + mi * 16 + g;
            #pragma unroll
            for (int ni = 0; ni < 4; ni++) {
                int col = n0 + wn * 32 + ni * 8 + 2 * tig;
                yw[((size_t)r0 * D_ + col) >> 1] =
                    pack_bf16(c[mi][ni][0], c[mi][ni][1]);
                yw[((size_t)(r0 + 8) * D_ + col) >> 1] =
                    pack_bf16(c[mi][ni][2], c[mi][ni][3]);
            }
        }

        if (mt + 1 < MT) {
            __syncthreads();    // all warps done reading As
            stA();
            __syncthreads();    // next A tile staged
        }
    }
}

// ---------------------------------------------------------------------------
// fused LIF kernel: grid (B, NCH) x 256 threads
// ---------------------------------------------------------------------------
template <bool GUARD>
__device__ __forceinline__ void lif1_main(const __nv_bfloat16* __restrict__ yp,
                                          const float* ac, float base,
                                          float& v, float& w0, float& w1,
                                          float& w2, float& w3, float& w4,
                                          float& w5, float& w6,
                                          int ts2, int tend, unsigned* smk,
                                          unsigned& locOr, int warp, int lane) {
    for (int t0 = ts2; t0 < tend; t0 += 4) {
        float nf[4];
        #pragma unroll
        for (int j = 0; j < 4; j++) {
            int t = t0 + 4 + j;
            if (GUARD)
                nf[j] = (t < T_) ? __bfloat162float(yp[(size_t)t * D_]) : 0.f;
            else
                nf[j] = __bfloat162float(yp[(size_t)t * D_]);
        }
        #pragma unroll
        for (int j = 0; j < 4; j++) {
            float acc = base;
            acc = fmaf(w0, ac[0], acc); acc = fmaf(w1, ac[1], acc);
            acc = fmaf(w2, ac[2], acc); acc = fmaf(w3, ac[3], acc);
            acc = fmaf(w4, ac[4], acc); acc = fmaf(w5, ac[5], acc);
            acc = fmaf(w6, ac[6], acc);
            v = fmaf(v, 0.5f, acc);
            bool s = (v >= 1.0f);
            unsigned bal = __ballot_sync(0xffffffffu, s);
            if (s) v = 0.f;
            if (lane == 0) { smk[(t0 + j - ts2) * 8 + warp] = bal; locOr |= bal; }
            w0 = w1; w1 = w2; w2 = w3; w3 = w4; w4 = w5; w5 = w6; w6 = nf[j];
        }
    }
}

__global__ __launch_bounds__(256) void k_lif(const float* __restrict__ pw_b,
                                             const float* __restrict__ dw,
                                             const float* __restrict__ g1,
                                             const float* __restrict__ b1,
                                             const float* __restrict__ m1,
                                             const float* __restrict__ v1,
                                             const float* __restrict__ g2,
                                             const float* __restrict__ b2,
                                             const float* __restrict__ m2,
                                             const float* __restrict__ v2p,
                                             float* __restrict__ out) {
    __shared__ unsigned smk[SMT * 8];
    __shared__ unsigned s_any;

    const int b    = blockIdx.x;
    const int ch   = blockIdx.y;
    const int d    = threadIdx.x;
    const int lane = d & 31;
    const int warp = d >> 5;

    const int tstart = ch * CLEN;
    const int tend   = tstart + CLEN;
    const int ts2    = (ch == 0) ? 0 : tstart - WARM2;
    const int ts1    = (ch == 0) ? 0 : ts2 - WARM1;

    if (d == 0) s_any = 0u;

    // ---- phase 1: depthwise conv + BN1 + LIF1 ----
    {
        const float bias  = pw_b[d];
        const float scale = g1[d] * rsqrtf(v1[d] + 1e-5f);
        const float shift = b1[d] - m1[d] * scale;

        float ac[K_];
        float suma = 0.f;
        #pragma unroll
        for (int k = 0; k < K_; k++) {
            float a = dw[d * K_ + k];
            suma += a;
            ac[k] = 0.5f * scale * a;
        }
        const float base = 0.5f * (scale * bias * suma + shift);

        const __nv_bfloat16* yp = g_ybf + (size_t)b * T_ * D_ + d;

        float w0, w1, w2, w3, w4, w5, w6;
        {
            float wv[7];
            #pragma unroll
            for (int j = 0; j < 7; j++) {
                int t = ts1 - 3 + j;
                wv[j] = (t >= 0) ? __bfloat162float(yp[(size_t)t * D_]) : 0.f;
            }
            w0 = wv[0]; w1 = wv[1]; w2 = wv[2]; w3 = wv[3];
            w4 = wv[4]; w5 = wv[5]; w6 = wv[6];
        }

        float v = 0.f;
        // speculative warmup [ts1, ts2): no writes
        for (int t0 = ts1; t0 < ts2; t0 += 4) {
            float nf[4];
            #pragma unroll
            for (int j = 0; j < 4; j++)
                nf[j] = __bfloat162float(yp[(size_t)(t0 + 4 + j) * D_]);
            #pragma unroll
            for (int j = 0; j < 4; j++) {
                float acc = base;
                acc = fmaf(w0, ac[0], acc); acc = fmaf(w1, ac[1], acc);
                acc = fmaf(w2, ac[2], acc); acc = fmaf(w3, ac[3], acc);
                acc = fmaf(w4, ac[4], acc); acc = fmaf(w5, ac[5], acc);
                acc = fmaf(w6, ac[6], acc);
                v = fmaf(v, 0.5f, acc);
                if (v >= 1.0f) v = 0.f;
                w0 = w1; w1 = w2; w2 = w3; w3 = w4; w4 = w5; w5 = w6; w6 = nf[j];
            }
        }

        unsigned locOr = 0u;
        if (ch == NCH - 1)
            lif1_main<true >(yp, ac, base, v, w0, w1, w2, w3, w4, w5, w6,
                             ts2, tend, smk, locOr, warp, lane);
        else
            lif1_main<false>(yp, ac, base, v, w0, w1, w2, w3, w4, w5, w6,
                             ts2, tend, smk, locOr, warp, lane);

        if (lane == 0 && locOr) atomicOr(&s_any, locOr);
    }
    __syncthreads();

    // ---- phase 2: sparse linear + BN2 + LIF2 + residual ----
    const int e = d;
    const float scale2 = g2[e] * rsqrtf(v2p[e] + 1e-5f);
    const float shift2 = b2[e] - m2[e] * scale2;

    float* op = out + (size_t)tstart * (B_ * D_) + (size_t)b * D_ + e;

    if (s_any == 0u) {
        if (shift2 < 1.0f) {
            #pragma unroll 10
            for (int j = 0; j < CLEN; ++j)
                op[(size_t)j * (B_ * D_)] = 0.f;
        } else {
            float v = 0.f;
            const float hs = 0.5f * shift2;
            for (int j = 0; j < tstart - ts2; ++j) {
                v = fmaf(v, 0.5f, hs);
                if (v >= 1.0f) v = 0.f;
            }
            #pragma unroll 10
            for (int j = 0; j < CLEN; ++j) {
                v = fmaf(v, 0.5f, hs);
                float sp = 0.f;
                if (v >= 1.0f) { sp = 1.f; v = 0.f; }
                op[(size_t)j * (B_ * D_)] = sp;
            }
        }
        return;
    }

    // slow path: spikes present in window
    const int      myw   = e >> 5;
    const unsigned mybit = 1u << (e & 31);
    float v = 0.f;

    for (int t = ts2; t < tend; ++t) {
        const int o = (t - ts2) * 8;
        uint4 p0 = *(const uint4*)&smk[o];
        uint4 p1 = *(const uint4*)&smk[o + 4];
        unsigned any = p0.x | p0.y | p0.z | p0.w | p1.x | p1.y | p1.z | p1.w;

        float acc = 0.f, res = 0.f;
        if (any) {
            unsigned wds[8] = {p0.x, p0.y, p0.z, p0.w, p1.x, p1.y, p1.z, p1.w};
            #pragma unroll
            for (int i = 0; i < 8; i++) {
                unsigned wd = wds[i];
                if (i == myw && (wd & mybit)) res = 1.f;
                while (wd) {
                    int bit = __ffs(wd) - 1;
                    wd &= wd - 1;
                    acc += g_linT[(size_t)(i * 32 + bit) * D_ + e];
                }
            }
        }

        float u = fmaf(acc, scale2, shift2);
        v = 0.5f * (v + u);
        float sp = 0.f;
        if (v >= 1.0f) { sp = 1.f; v = 0.f; }

        if (t >= tstart)
            out[((size_t)t * B_ + b) * D_ + e] = sp + res;
    }
}

// ---------------------------------------------------------------------------
// inputs: 0:x 1:pw_w 2:pw_b 3:dw_w 4:bn1_g 5:bn1_b 6:bn1_m 7:bn1_v
//         8:lin_w 9:bn2_g 10:bn2_b 11:bn2_m 12:bn2_v
// ---------------------------------------------------------------------------
extern "C" void kernel_launch(void* const* d_in, const int* in_sizes, int n_in,
                              void* d_out, int out_size) {
    const float* x    = (const float*)d_in[0];
    const float* pw_w = (const float*)d_in[1];
    const float* pw_b = (const float*)d_in[2];
    const float* dw_w = (const float*)d_in[3];
    const float* g1   = (const float*)d_in[4];
    const float* b1   = (const float*)d_in[5];
    const float* m1   = (const float*)d_in[6];
    const float* v1   = (const float*)d_in[7];
    const float* linw = (const float*)d_in[8];
    const float* g2   = (const float*)d_in[9];
    const float* b2   = (const float*)d_in[10];
    const float* m2   = (const float*)d_in[11];
    const float* v2   = (const float*)d_in[12];
    float* out = (float*)d_out;

    cudaFuncSetAttribute(k_gemm1, cudaFuncAttributeMaxDynamicSharedMemorySize,
                         GSM_BYTES);

    dim3 gg((B_ * T_) / (MT * 64), D_ / 128);   // (500, 2)
    k_gemm1<<<gg, 256, GSM_BYTES>>>(x, pw_w, linw);

    dim3 gl(B_, NCH);
    k_lif<<<gl, 256>>>(pw_b, dw_w, g1, b1, m1, v1, g2, b2, m2, v2, out);
}